// round 7
// baseline (speedup 1.0000x reference)
#include <cuda_runtime.h>
#include <cuda_fp16.h>
#include <cstdint>

// ---------------- problem shape ----------------
#define TOK   32768
#define HDIM  4096
#define NE    64
#define BM    128            // tokens per CTA
#define BK    64             // k per chunk
#define NCH   64             // HDIM / BK
#define NT    256            // threads (8 warps, 1 m-tile each)
#define TAU   2.5e-3f
#define RSCALE 2048.0f       // residual plane pre-scale (2^11, keeps fp16 normal)
#define RINV  (1.0f / 2048.0f)

// smem per buffer (SW128-swizzled, 128B rows):
//  XH[128][128B fp16] @ 0      (16384 B)
//  WH[64][128B]       @ 16384  (8192 B)
//  WL[64][128B]       @ 24576  (8192 B)
#define XH_OFF 0
#define WH_OFF 16384
#define WL_OFF 24576
#define BUFB   32768
#define SMEMB  (2 * BUFB)    // 65536 bytes

// ---------------- device globals ----------------
// g_w: [chunk 64][plane 2 (h, l*2^11)][expert 64][64 fp16 = 128B]
__device__ uint32_t g_w[NCH * 2 * 2048];
__device__ int g_flag_count;
__device__ int g_flag_list[TOK];

// ---------------- helpers ----------------
__device__ __forceinline__ uint32_t s2u(const void* p) {
    uint32_t a;
    asm("{ .reg .u64 t; cvta.to.shared.u64 t, %1; cvt.u32.u64 %0, t; }" : "=r"(a) : "l"(p));
    return a;
}
__device__ __forceinline__ uint32_t sw128(uint32_t o) { return o ^ ((o >> 3) & 0x70); }

// pack {lo=f0, hi=f1} as fp16x2
__device__ __forceinline__ uint32_t cvt2h(float f0, float f1) {
    __half2 h = __floats2half2_rn(f0, f1);
    return *reinterpret_cast<uint32_t*>(&h);
}
__device__ __forceinline__ void ldsm4(uint32_t* r, uint32_t addr) {
    asm volatile("ldmatrix.sync.aligned.m8n8.x4.shared.b16 {%0,%1,%2,%3}, [%4];"
                 : "=r"(r[0]), "=r"(r[1]), "=r"(r[2]), "=r"(r[3]) : "r"(addr));
}
__device__ __forceinline__ void mma16816(float* c, const uint32_t* a,
                                         uint32_t b0, uint32_t b1) {
    asm("mma.sync.aligned.m16n8k16.row.col.f32.f16.f16.f32 "
        "{%0,%1,%2,%3}, {%4,%5,%6,%7}, {%8,%9}, {%0,%1,%2,%3};"
        : "+f"(c[0]), "+f"(c[1]), "+f"(c[2]), "+f"(c[3])
        : "r"(a[0]), "r"(a[1]), "r"(a[2]), "r"(a[3]), "r"(b0), "r"(b1));
}
__device__ __forceinline__ void cpasync16(uint32_t dst, const void* src) {
    asm volatile("cp.async.ca.shared.global [%0], [%1], 16;" :: "r"(dst), "l"(src));
}
#define CP_COMMIT() asm volatile("cp.async.commit_group;" ::: "memory")
#define CP_WAIT0()  asm volatile("cp.async.wait_group 0;" ::: "memory")

// ---------------- prep: W fp32 -> fp16 h + fp16 scaled residual ----------------
__global__ void prep_w(const float* __restrict__ W) {
    int id = blockIdx.x * 256 + threadIdx.x;      // 32768 threads
    if (id == 0) g_flag_count = 0;
    if (id >= 32768) return;
    int e = id >> 9;                // expert 0..63
    int kk = id & 511;              // 8-value group
    int k = kk * 8;
    int c = k >> 6, kc = k & 63;
    const float4* src = (const float4*)(W + (size_t)e * HDIM + k);
    float4 v0 = src[0], v1 = src[1];

    uint32_t h[4], l[4];
    float f[8] = {v0.x, v0.y, v0.z, v0.w, v1.x, v1.y, v1.z, v1.w};
#pragma unroll
    for (int p = 0; p < 4; ++p) {
        uint32_t hp = cvt2h(f[2 * p], f[2 * p + 1]);
        __half2 hh = *reinterpret_cast<__half2*>(&hp);
        float2 hf = __half22float2(hh);
        h[p] = hp;
        // residual scaled by 2^11 so it stays NORMAL in fp16 (subnormal inputs
        // to the tensor pipe trigger a slow path — round-6 lesson)
        l[p] = cvt2h((f[2 * p] - hf.x) * RSCALE, (f[2 * p + 1] - hf.y) * RSCALE);
    }
    uint32_t* dh = g_w + ((size_t)(c * 2 + 0) * 64 + e) * 32 + (kc >> 1);
    uint32_t* dl = g_w + ((size_t)(c * 2 + 1) * 64 + e) * 32 + (kc >> 1);
    *(uint4*)dh = make_uint4(h[0], h[1], h[2], h[3]);
    *(uint4*)dl = make_uint4(l[0], l[1], l[2], l[3]);
}

// ---------------- main: fp16 2-pass HMMA GEMM + fused softmax/top2 ----------------
__global__ void __launch_bounds__(NT, 2)
moe_gate_mma(const float* __restrict__ X, float* __restrict__ out) {
    extern __shared__ char smem_raw[];
    const uint32_t sbase = s2u(smem_raw);

    const int tid  = threadIdx.x;
    const int lane = tid & 31, wid = tid >> 5;       // 8 warps
    const int lrow = lane & 15, lkh = lane >> 4;
    const int tok0 = blockIdx.x * BM;
    const float* Xg = X + (size_t)tok0 * HDIM;

    // ldmatrix lane base addresses; ks applied via XOR (32B per kstep)
    const int arow = wid * 16 + lrow;
    const uint32_t aSw = (uint32_t)(arow * 128) +
                         (((uint32_t)(lkh * 16)) ^ ((uint32_t)(arow & 7) << 4));
    const uint32_t aH = sbase + XH_OFF + aSw;
    uint32_t bH[4], bL[4];
#pragma unroll
    for (int np = 0; np < 4; ++np) {
        int brow = np * 16 + lrow;
        uint32_t bSw = (uint32_t)(brow * 128) +
                       (((uint32_t)(lkh * 16)) ^ ((uint32_t)(brow & 7) << 4));
        bH[np] = sbase + WH_OFF + bSw;
        bL[np] = sbase + WL_OFF + bSw;
    }

    float accH[8][4], accL[8][4];
#pragma unroll
    for (int nt = 0; nt < 8; ++nt)
#pragma unroll
        for (int q = 0; q < 4; ++q) { accH[nt][q] = 0.0f; accL[nt][q] = 0.0f; }

    float4 xa[8];

#define LDG_X(cc)                                                               \
    {                                                                           \
        const int kb = (cc) * BK;                                               \
        _Pragma("unroll")                                                       \
        for (int it = 0; it < 8; ++it) {                                        \
            int f = it * NT + tid;                                              \
            int row = f >> 4, k4 = f & 15;                                      \
            xa[it] = *(const float4*)(Xg + (size_t)row * HDIM + kb + k4 * 4);   \
        }                                                                       \
    }

#define CP_W(cc, bufo)                                                          \
    {                                                                           \
        const char* wsrc = (const char*)g_w + (size_t)(cc) * 16384;             \
        _Pragma("unroll")                                                       \
        for (int q = 0; q < 4; ++q) {                                           \
            int idx = q * NT + tid;            /* 0..1023 */                    \
            int pl = idx >> 9, rest = idx & 511;                                \
            int row = rest >> 3, blk = rest & 7;                                \
            uint32_t dst = sbase + (bufo) + WH_OFF + pl * 8192 +                \
                           sw128((uint32_t)(row * 128 + blk * 16));             \
            cpasync16(dst, wsrc + pl * 8192 + row * 128 + blk * 16);            \
        }                                                                       \
        CP_COMMIT();                                                            \
    }

#define CVT_X(bufo)                                                             \
    {                                                                           \
        _Pragma("unroll")                                                       \
        for (int it = 0; it < 8; ++it) {                                        \
            int f = it * NT + tid;                                              \
            int row = f >> 4, k4 = f & 15;                                      \
            uint32_t h0 = cvt2h(xa[it].x, xa[it].y);                            \
            uint32_t h1 = cvt2h(xa[it].z, xa[it].w);                            \
            uint32_t sw = sw128((uint32_t)(row * 128 + k4 * 8));                \
            *(uint2*)(smem_raw + (bufo) + XH_OFF + sw) = make_uint2(h0, h1);    \
        }                                                                       \
    }

    // ---- stage chunk 0 ----
    LDG_X(0);
    CP_W(0, 0);
    CVT_X(0);
    CP_WAIT0();
    __syncthreads();

    // ---- main loop over 64 chunks ----
    for (int c = 0; c < NCH; ++c) {
        const uint32_t bufR = (uint32_t)(c & 1) * BUFB;
        const uint32_t bufW = (uint32_t)((c + 1) & 1) * BUFB;
        const bool more = (c + 1 < NCH);

        if (more) {
            LDG_X(c + 1);
            CP_W(c + 1, bufW);
        }

        // mma: 4 ksteps x 4 np-tiles x 2 sub x 2 passes = 64
#pragma unroll
        for (int ks = 0; ks < 4; ++ks) {
            const uint32_t kx = (uint32_t)(ks * 32);
            uint32_t Ah[4];
            ldsm4(Ah, (aH + bufR) ^ kx);
#pragma unroll
            for (int np = 0; np < 4; ++np) {
                uint32_t Bh[4], Bl[4];
                ldsm4(Bh, (bH[np] + bufR) ^ kx);
                ldsm4(Bl, (bL[np] + bufR) ^ kx);
#pragma unroll
                for (int sub = 0; sub < 2; ++sub) {
                    mma16816(accH[np * 2 + sub], Ah, Bh[sub], Bh[2 + sub]); // x*h
                    mma16816(accL[np * 2 + sub], Ah, Bl[sub], Bl[2 + sub]); // x*l'
                }
            }
        }

        if (more) {
            CVT_X(bufW);
            CP_WAIT0();
        }
        __syncthreads();
    }

    // ---- combine planes: logit = accH + accL * 2^-11 ----
#pragma unroll
    for (int nt = 0; nt < 8; ++nt)
#pragma unroll
        for (int q = 0; q < 4; ++q) accH[nt][q] = fmaf(accL[nt][q], RINV, accH[nt][q]);

    // ---- scatter logits into smem overlay lg[128][65] ----
    float* lg = (float*)smem_raw;
    const int g = lane >> 2, tig = lane & 3;
#pragma unroll
    for (int nt = 0; nt < 8; ++nt) {
        int r0 = wid * 16 + g;
        int e0 = nt * 8 + tig * 2;
        lg[r0 * 65 + e0]           = accH[nt][0];
        lg[r0 * 65 + e0 + 1]       = accH[nt][1];
        lg[(r0 + 8) * 65 + e0]     = accH[nt][2];
        lg[(r0 + 8) * 65 + e0 + 1] = accH[nt][3];
    }
    __syncthreads();

    // ---- per-token softmax + top-3 + near-tie flag (threads 0..127) ----
    if (tid < BM) {
        const int t = tid;
        const float* row = lg + t * 65;
        float mx = row[0];
#pragma unroll 8
        for (int e = 1; e < NE; ++e) mx = fmaxf(mx, row[e]);
        float sum = 0.0f;
        float s1 = -3.4e38f, s2 = -3.4e38f, s3 = -3.4e38f;
        int i1 = 0, i2 = 0;
#pragma unroll 8
        for (int e = 0; e < NE; ++e) {
            float l = row[e];
            sum += expf(l - mx);
            if (l > s1)      { s3 = s2; s2 = s1; i2 = i1; s1 = l; i1 = e; }
            else if (l > s2) { s3 = s2; s2 = l; i2 = e; }
            else if (l > s3) { s3 = l; }
        }
        float inv = 1.0f / sum;
        int gt = tok0 + t;
        out[2 * gt]               = (float)i1;
        out[2 * gt + 1]           = (float)i2;
        out[2 * TOK + 2 * gt]     = expf(s1 - mx) * inv;
        out[2 * TOK + 2 * gt + 1] = expf(s2 - mx) * inv;
        if ((s1 - s2 < TAU) || (s2 - s3 < TAU)) {
            int sl = atomicAdd(&g_flag_count, 1);
            if (sl < TOK) g_flag_list[sl] = gt;
        }
    }
}

// ---------------- cleanup: fp64 recompute of near-tie tokens (8-way ILP) ----------------
__global__ void cleanup_kernel(const float* __restrict__ X, const float* __restrict__ W,
                               float* __restrict__ out) {
    __shared__ double sred[128];
    __shared__ double lgs[64];
    int nf = g_flag_count;
    if (nf > TOK) nf = TOK;
    for (int i = blockIdx.x; i < nf; i += gridDim.x) {
        int t = g_flag_list[i];
        int e  = threadIdx.x & 63;
        int kh = threadIdx.x >> 6;
        const float4* xr = (const float4*)(X + (size_t)t * HDIM + kh * 2048);
        const float4* wr = (const float4*)(W + (size_t)e * HDIM + kh * 2048);
        double a0 = 0, a1 = 0, a2 = 0, a3 = 0, a4 = 0, a5 = 0, a6 = 0, a7 = 0;
#pragma unroll 4
        for (int q = 0; q < 512; q += 2) {
            float4 x0 = xr[q],     w0 = wr[q];
            float4 x1 = xr[q + 1], w1 = wr[q + 1];
            a0 += (double)x0.x * w0.x;  a1 += (double)x0.y * w0.y;
            a2 += (double)x0.z * w0.z;  a3 += (double)x0.w * w0.w;
            a4 += (double)x1.x * w1.x;  a5 += (double)x1.y * w1.y;
            a6 += (double)x1.z * w1.z;  a7 += (double)x1.w * w1.w;
        }
        sred[threadIdx.x] = ((a0 + a1) + (a2 + a3)) + ((a4 + a5) + (a6 + a7));
        __syncthreads();
        if (threadIdx.x < 64) lgs[threadIdx.x] = sred[threadIdx.x] + sred[threadIdx.x + 64];
        __syncthreads();
        if (threadIdx.x == 0) {
            double mx = lgs[0];
            for (int q = 1; q < NE; ++q) if (lgs[q] > mx) mx = lgs[q];
            double sum = 0.0;
            double s1 = -1e300, s2 = -1e300;
            int i1 = 0, i2 = 0;
            for (int q = 0; q < NE; ++q) {
                double l = lgs[q];
                sum += exp(l - mx);
                if (l > s1)      { s2 = s1; i2 = i1; s1 = l; i1 = q; }
                else if (l > s2) { s2 = l; i2 = q; }
            }
            double inv = 1.0 / sum;
            out[2 * t]               = (float)i1;
            out[2 * t + 1]           = (float)i2;
            out[2 * TOK + 2 * t]     = (float)(exp(s1 - mx) * inv);
            out[2 * TOK + 2 * t + 1] = (float)(exp(s2 - mx) * inv);
        }
        __syncthreads();
    }
}

// ---------------- launch ----------------
extern "C" void kernel_launch(void* const* d_in, const int* in_sizes, int n_in,
                              void* d_out, int out_size) {
    const float* X = (const float*)d_in[0];
    const float* W = (const float*)d_in[1];
    float* out = (float*)d_out;

    static bool once = []() {
        cudaFuncSetAttribute(moe_gate_mma, cudaFuncAttributeMaxDynamicSharedMemorySize,
                             SMEMB);
        return true;
    }();
    (void)once;

    prep_w<<<128, 256>>>(W);
    moe_gate_mma<<<TOK / BM, NT, SMEMB>>>(X, out);
    cleanup_kernel<<<256, 128>>>(X, W, out);
}

// round 8
// speedup vs baseline: 1.0583x; 1.0583x over previous
#include <cuda_runtime.h>
#include <cstdint>

// ---------------- problem shape ----------------
#define TOK   32768
#define HDIM  4096
#define NE    64
#define BM    64             // tokens per CTA
#define BK    32             // k per chunk
#define NCH   128            // HDIM / BK
#define NT    64             // threads (2 warps)
#define TAU   1e-4f

// smem (words): xs0 xs1 ws0 ws1, each [BK][68] (stride 68 = conflict-free + 16B aligned)
#define STR    68
#define BUFW   (BK * STR)            // 2176 words
#define XS0    0
#define XS1    BUFW
#define WS0    (2 * BUFW)
#define WS1    (3 * BUFW)
#define SMW    (4 * BUFW)            // 8704 words = 34816 B  (< 48KB, static)

// ---------------- device globals ----------------
__device__ float g_wt[HDIM * NE];    // W transposed: [k][e]
__device__ int g_flag_count;
__device__ int g_flag_list[TOK];

// ---------------- packed fp32x2 ops (opaque to the compiler) ----------------
#define FMA2(d, a, b) \
    asm("fma.rn.f32x2 %0, %1, %2, %0;" : "+l"(d) : "l"(a), "l"(b))
#define DUP2(d, s) \
    asm("mov.b64 %0, {%1, %1};" : "=l"(d) : "f"(s))
#define UNPK2(lo, hi, p) \
    asm("mov.b64 {%0, %1}, %2;" : "=f"(lo), "=f"(hi) : "l"(p))

__device__ __forceinline__ uint32_t s2u(const void* p) {
    uint32_t a;
    asm("{ .reg .u64 t; cvta.to.shared.u64 t, %1; cvt.u32.u64 %0, t; }" : "=r"(a) : "l"(p));
    return a;
}
__device__ __forceinline__ void cpasync16(uint32_t dst, const void* src) {
    asm volatile("cp.async.ca.shared.global [%0], [%1], 16;" :: "r"(dst), "l"(src));
}
#define CP_COMMIT() asm volatile("cp.async.commit_group;" ::: "memory")
#define CP_WAIT0()  asm volatile("cp.async.wait_group 0;" ::: "memory")

// ---------------- prep: transpose W -> g_wt[k][e] ----------------
__global__ void prep_wt(const float* __restrict__ W) {
    int id = blockIdx.x * 256 + threadIdx.x;     // 262144 threads
    if (id == 0) g_flag_count = 0;
    if (id >= HDIM * NE) return;
    int k = id >> 6, e = id & 63;
    g_wt[id] = W[(size_t)e * HDIM + k];
}

// ---------------- main: fp32 FFMA2 GEMM + fused softmax/top2 ----------------
__global__ void __launch_bounds__(NT)
moe_gate_ffma(const float* __restrict__ X, float* __restrict__ out) {
    __shared__ __align__(16) float sm[SMW];
    const uint32_t sbase = s2u(sm);

    const int tid  = threadIdx.x;
    const int lane = tid & 31, wid = tid >> 5;
    const int tg   = lane >> 2;          // 0..7 token group
    const int eg   = lane & 3;           // 0..3 expert group
    const int tok0 = blockIdx.x * BM;

    // this thread's x row (thread == token for loading)
    const float4* Xrow = (const float4*)(X + (size_t)(tok0 + tid) * HDIM);

    // acc[i][t] = (logit[token t][expert e], logit[t][e+1]),  e = eg*16 + 2i
    uint64_t acc[8][4];
#pragma unroll
    for (int i = 0; i < 8; ++i)
#pragma unroll
        for (int t = 0; t < 4; ++t) acc[i][t] = 0ull;

    float4 xa[8];

#define LDG_X(cc)                                                         \
    {                                                                     \
        _Pragma("unroll")                                                 \
        for (int it = 0; it < 8; ++it) xa[it] = Xrow[(cc) * 8 + it];      \
    }

#define STS_X(xoff)                                                       \
    {                                                                     \
        float* xd_ = sm + (xoff);                                         \
        _Pragma("unroll")                                                 \
        for (int it = 0; it < 8; ++it) {                                  \
            xd_[(it * 4 + 0) * STR + tid] = xa[it].x;                     \
            xd_[(it * 4 + 1) * STR + tid] = xa[it].y;                     \
            xd_[(it * 4 + 2) * STR + tid] = xa[it].z;                     \
            xd_[(it * 4 + 3) * STR + tid] = xa[it].w;                     \
        }                                                                 \
    }

#define CP_W(cc, woff)                                                    \
    {                                                                     \
        const char* wsrc = (const char*)(g_wt + (size_t)(cc) * BK * 64);  \
        _Pragma("unroll")                                                 \
        for (int q = 0; q < 8; ++q) {                                     \
            int idx = q * NT + tid;        /* 0..511 */                   \
            int k = idx >> 4, f4 = idx & 15;                              \
            cpasync16(sbase + ((woff) + k * STR + f4 * 4) * 4,            \
                      wsrc + (k * 64 + f4 * 4) * 4);                      \
        }                                                                 \
        CP_COMMIT();                                                      \
    }

    // ---- stage chunk 0 ----
    LDG_X(0);
    CP_W(0, WS0);
    STS_X(XS0);
    CP_WAIT0();
    __syncthreads();

    const int xrd = wid * 32 + tg * 4;        // x read offset within row
    const int wrd = eg * 16;                  // w read offset within row

    for (int c = 0; c < NCH; ++c) {
        const int xcur = (c & 1) ? XS1 : XS0;
        const int wcur = (c & 1) ? WS1 : WS0;
        const int xnxt = (c & 1) ? XS0 : XS1;
        const int wnxt = (c & 1) ? WS0 : WS1;
        const bool more = (c + 1 < NCH);

        if (more) {
            LDG_X(c + 1);
            CP_W(c + 1, wnxt);
        }

        const float* xr = sm + xcur + xrd;
        const float* wr = sm + wcur + wrd;
#pragma unroll 8
        for (int kk = 0; kk < BK; ++kk) {
            float4 xv = *(const float4*)(xr + kk * STR);
            uint64_t xd[4];
            DUP2(xd[0], xv.x);
            DUP2(xd[1], xv.y);
            DUP2(xd[2], xv.z);
            DUP2(xd[3], xv.w);
            uint64_t wp[8];
#pragma unroll
            for (int i = 0; i < 8; ++i)
                wp[i] = *(const uint64_t*)(wr + kk * STR + 2 * i);
#pragma unroll
            for (int i = 0; i < 8; ++i)
#pragma unroll
                for (int t = 0; t < 4; ++t)
                    FMA2(acc[i][t], xd[t], wp[i]);
        }

        if (more) {
            STS_X(xnxt);
            CP_WAIT0();
        }
        __syncthreads();
    }

    // ---- scatter logits into smem overlay lg[64][66] ----
    float* lg = sm;
#pragma unroll
    for (int i = 0; i < 8; ++i) {
        int e = eg * 16 + 2 * i;
#pragma unroll
        for (int t = 0; t < 4; ++t) {
            int tt = wid * 32 + tg * 4 + t;
            *(uint64_t*)(lg + tt * 66 + e) = acc[i][t];   // 8B-aligned (66 even, e even)
        }
    }
    __syncthreads();

    // ---- per-token softmax + top-3 + near-tie flag (1 thread / token) ----
    {
        const int t = tid;
        const float* row = lg + t * 66;
        float mx = row[0];
#pragma unroll 8
        for (int e = 1; e < NE; ++e) mx = fmaxf(mx, row[e]);
        float sum = 0.0f;
        float s1 = -3.4e38f, s2 = -3.4e38f, s3 = -3.4e38f;
        int i1 = 0, i2 = 0;
#pragma unroll 8
        for (int e = 0; e < NE; ++e) {
            float l = row[e];
            sum += expf(l - mx);
            if (l > s1)      { s3 = s2; s2 = s1; i2 = i1; s1 = l; i1 = e; }
            else if (l > s2) { s3 = s2; s2 = l; i2 = e; }
            else if (l > s3) { s3 = l; }
        }
        float inv = 1.0f / sum;
        int gt = tok0 + t;
        out[2 * gt]               = (float)i1;
        out[2 * gt + 1]           = (float)i2;
        out[2 * TOK + 2 * gt]     = expf(s1 - mx) * inv;
        out[2 * TOK + 2 * gt + 1] = expf(s2 - mx) * inv;
        if ((s1 - s2 < TAU) || (s2 - s3 < TAU)) {
            int sl = atomicAdd(&g_flag_count, 1);
            if (sl < TOK) g_flag_list[sl] = gt;
        }
    }
}

// ---------------- cleanup: fp64 recompute of near-tie tokens (8-way ILP) ----------------
__global__ void cleanup_kernel(const float* __restrict__ X, const float* __restrict__ W,
                               float* __restrict__ out) {
    __shared__ double sred[128];
    __shared__ double lgs[64];
    int nf = g_flag_count;
    if (nf > TOK) nf = TOK;
    for (int i = blockIdx.x; i < nf; i += gridDim.x) {
        int t = g_flag_list[i];
        int e  = threadIdx.x & 63;
        int kh = threadIdx.x >> 6;
        const float4* xr = (const float4*)(X + (size_t)t * HDIM + kh * 2048);
        const float4* wr = (const float4*)(W + (size_t)e * HDIM + kh * 2048);
        double a0 = 0, a1 = 0, a2 = 0, a3 = 0, a4 = 0, a5 = 0, a6 = 0, a7 = 0;
#pragma unroll 4
        for (int q = 0; q < 512; q += 2) {
            float4 x0 = xr[q],     w0 = wr[q];
            float4 x1 = xr[q + 1], w1 = wr[q + 1];
            a0 += (double)x0.x * w0.x;  a1 += (double)x0.y * w0.y;
            a2 += (double)x0.z * w0.z;  a3 += (double)x0.w * w0.w;
            a4 += (double)x1.x * w1.x;  a5 += (double)x1.y * w1.y;
            a6 += (double)x1.z * w1.z;  a7 += (double)x1.w * w1.w;
        }
        sred[threadIdx.x] = ((a0 + a1) + (a2 + a3)) + ((a4 + a5) + (a6 + a7));
        __syncthreads();
        if (threadIdx.x < 64) lgs[threadIdx.x] = sred[threadIdx.x] + sred[threadIdx.x + 64];
        __syncthreads();
        if (threadIdx.x == 0) {
            double mx = lgs[0];
            for (int q = 1; q < NE; ++q) if (lgs[q] > mx) mx = lgs[q];
            double sum = 0.0;
            double s1 = -1e300, s2 = -1e300;
            int i1 = 0, i2 = 0;
            for (int q = 0; q < NE; ++q) {
                double l = lgs[q];
                sum += exp(l - mx);
                if (l > s1)      { s2 = s1; i2 = i1; s1 = l; i1 = q; }
                else if (l > s2) { s2 = l; i2 = q; }
            }
            double inv = 1.0 / sum;
            out[2 * t]               = (float)i1;
            out[2 * t + 1]           = (float)i2;
            out[2 * TOK + 2 * t]     = (float)(exp(s1 - mx) * inv);
            out[2 * TOK + 2 * t + 1] = (float)(exp(s2 - mx) * inv);
        }
        __syncthreads();
    }
}

// ---------------- launch ----------------
extern "C" void kernel_launch(void* const* d_in, const int* in_sizes, int n_in,
                              void* d_out, int out_size) {
    const float* X = (const float*)d_in[0];
    const float* W = (const float*)d_in[1];
    float* out = (float*)d_out;

    prep_wt<<<1024, 256>>>(W);
    moe_gate_ffma<<<TOK / BM, NT>>>(X, out);
    cleanup_kernel<<<256, 128>>>(X, W, out);
}